// round 8
// baseline (speedup 1.0000x reference)
#include <cuda_runtime.h>
#include <stdint.h>

#define NMAX 50000
#define DD 128
#define NPW 8   // nodes per warp in proj-dot
#define EPT 8   // edges per thread in edge sweeps

// Scratch (no device allocs allowed)
__device__ int   g_mode;        // 1 = indices are int64, 0 = int32
__device__ float g_deg[NMAX];
__device__ float g_y[NMAX];     // x . W
__device__ float g_p[NMAX];
__device__ float g_q[NMAX];     // p * y   (hop-1 message value)
__device__ float g_r[NMAX];     // p * t   (hop-2 message value)
__device__ float g_acc1[NMAX];  // sum of q[src] per dst
__device__ float g_acc2[NMAX];  // sum of r[src] per dst

// ---------------------------------------------------------------------------
// K1: detect dtype (warp 0 of block 0) + deg[i]=1 + zero accumulators
__global__ void k_init(const long long* __restrict__ edge, int n) {
    if (blockIdx.x == 0 && threadIdx.x < 32) {
        long long v = edge[threadIdx.x];
        unsigned ok = __ballot_sync(0xffffffffu, v >= 0 && v < (long long)n);
        if (threadIdx.x == 0) g_mode = (ok == 0xffffffffu) ? 1 : 0;
    }
    int i = blockIdx.x * blockDim.x + threadIdx.x;
    if (i < n) {
        g_deg[i]  = 1.0f;
        g_acc1[i] = 0.0f;
        g_acc2[i] = 0.0f;
    }
}

// ---------------------------------------------------------------------------
// Load EPT=8 indices starting at edge index base (mode-dependent).
__device__ __forceinline__ void load_idx8(const long long* __restrict__ edge,
                                          int base, int mode, int off,
                                          int idx[EPT]) {
    if (mode) {
        const longlong2* v = (const longlong2*)(edge + off) + (base >> 1);
        longlong2 a = v[0], b = v[1], c = v[2], d = v[3];
        idx[0] = (int)a.x; idx[1] = (int)a.y;
        idx[2] = (int)b.x; idx[3] = (int)b.y;
        idx[4] = (int)c.x; idx[5] = (int)c.y;
        idx[6] = (int)d.x; idx[7] = (int)d.y;
    } else {
        const int* e32 = (const int*)edge;
        const int4* v = (const int4*)(e32 + off) + (base >> 2);
        int4 a = v[0], b = v[1];
        idx[0] = a.x; idx[1] = a.y; idx[2] = a.z; idx[3] = a.w;
        idx[4] = b.x; idx[5] = b.y; idx[6] = b.z; idx[7] = b.w;
    }
}

// ---------------------------------------------------------------------------
// K2 (fused, block-specialized):
//   blocks [0, edgeBlocks)          : deg[dst] += 1 over edges (atomic pipe)
//   blocks [edgeBlocks, ...)        : y[node] = x[node] . W    (DRAM pipe)
__global__ void k_deg_dot(const float* __restrict__ x, const float* __restrict__ W,
                          const long long* __restrict__ edge,
                          int e_cnt, int n, int edgeBlocks) {
    if (blockIdx.x < edgeBlocks) {
        // ---- degree count ----
        int t = blockIdx.x * blockDim.x + threadIdx.x;
        int nvec = e_cnt / EPT;
        int mode = g_mode;
        if (t < nvec) {
            int d[EPT];
            load_idx8(edge, t * EPT, mode, e_cnt, d);
            #pragma unroll
            for (int k = 0; k < EPT; k++)
                if ((unsigned)d[k] < (unsigned)n) atomicAdd(&g_deg[d[k]], 1.0f);
        } else if (t == nvec) {
            for (int e = nvec * EPT; e < e_cnt; e++) {
                int dst = mode ? (int)edge[e_cnt + e] : ((const int*)edge)[e_cnt + e];
                if ((unsigned)dst < (unsigned)n) atomicAdd(&g_deg[dst], 1.0f);
            }
        }
    } else {
        // ---- projection dot product: warp handles NPW nodes ----
        int bid = blockIdx.x - edgeBlocks;
        int warp = (bid * blockDim.x + threadIdx.x) >> 5;
        int lane = threadIdx.x & 31;
        int base = warp * NPW;
        if (base >= n) return;

        float4 w = __ldg(&((const float4*)W)[lane]);

        float4 a[NPW];
        #pragma unroll
        for (int k = 0; k < NPW; k++) {
            int node = base + k;
            if (node < n)
                a[k] = ((const float4*)(x + (size_t)node * DD))[lane];
            else
                a[k] = make_float4(0.f, 0.f, 0.f, 0.f);
        }

        float s[NPW];
        #pragma unroll
        for (int k = 0; k < NPW; k++)
            s[k] = a[k].x * w.x + a[k].y * w.y + a[k].z * w.z + a[k].w * w.w;

        #pragma unroll
        for (int off = 16; off > 0; off >>= 1) {
            #pragma unroll
            for (int k = 0; k < NPW; k++)
                s[k] += __shfl_down_sync(0xffffffffu, s[k], off);
        }

        if (lane == 0) {
            #pragma unroll
            for (int k = 0; k < NPW; k++) {
                int node = base + k;
                if (node < n) g_y[node] = s[k];
            }
        }
    }
}

// ---------------------------------------------------------------------------
// K3: p = rsqrt(deg), q = p*y   (tiny)
__global__ void k_pq(int n) {
    int i = blockIdx.x * blockDim.x + threadIdx.x;
    if (i < n) {
        float p = rsqrtf(g_deg[i]);
        g_p[i] = p;
        g_q[i] = p * g_y[i];
    }
}

// ---------------------------------------------------------------------------
// Edge sweep: acc[dst] += val[src].  EPT edges/thread.
__device__ __forceinline__ void edge_sweep(const long long* __restrict__ edge,
                                           int e_cnt, int n,
                                           const float* __restrict__ val,
                                           float* __restrict__ acc) {
    int t = blockIdx.x * blockDim.x + threadIdx.x;
    int nvec = e_cnt / EPT;
    int mode = g_mode;
    if (t < nvec) {
        int s[EPT], d[EPT];
        load_idx8(edge, t * EPT, mode, 0, s);
        load_idx8(edge, t * EPT, mode, e_cnt, d);
        bool ok[EPT];
        float v[EPT];
        #pragma unroll
        for (int k = 0; k < EPT; k++) {
            ok[k] = (unsigned)s[k] < (unsigned)n && (unsigned)d[k] < (unsigned)n;
            v[k] = ok[k] ? val[s[k]] : 0.f;
        }
        #pragma unroll
        for (int k = 0; k < EPT; k++)
            if (ok[k]) atomicAdd(&acc[d[k]], v[k]);
    } else if (t == nvec) {
        for (int e = nvec * EPT; e < e_cnt; e++) {
            int src = mode ? (int)edge[e] : ((const int*)edge)[e];
            int dst = mode ? (int)edge[e_cnt + e] : ((const int*)edge)[e_cnt + e];
            if ((unsigned)src < (unsigned)n && (unsigned)dst < (unsigned)n)
                atomicAdd(&acc[dst], val[src]);
        }
    }
}

__global__ void k_hop1(const long long* __restrict__ edge, int e_cnt, int n) {
    edge_sweep(edge, e_cnt, n, g_q, g_acc1);
}

__global__ void k_hop2(const long long* __restrict__ edge, int e_cnt, int n) {
    edge_sweep(edge, e_cnt, n, g_r, g_acc2);
}

// ---------------------------------------------------------------------------
// K5: r = p*p*(q + acc1)
__global__ void k_mid(int n) {
    int i = blockIdx.x * blockDim.x + threadIdx.x;
    if (i < n) {
        float p = g_p[i];
        g_r[i] = p * p * (g_q[i] + g_acc1[i]);
    }
}

// K7: out[i] = p*(r + acc2) + b
__global__ void k_final(float* __restrict__ out, const float* __restrict__ b, int n) {
    int i = blockIdx.x * blockDim.x + threadIdx.x;
    if (i < n) {
        out[i] = g_p[i] * (g_r[i] + g_acc2[i]) + b[0];
    }
}

extern "C" void kernel_launch(void* const* d_in, const int* in_sizes, int n_in,
                              void* d_out, int out_size) {
    const float*     x    = (const float*)d_in[0];       // [N, 128]
    const long long* edge = (const long long*)d_in[1];   // [2, E] indices
    const float*     W    = (const float*)d_in[2];       // [1, 128]
    const float*     b    = (const float*)d_in[3];       // [1]
    float*           out  = (float*)d_out;               // [N]

    int n = in_sizes[0] / DD;
    if (n > NMAX) n = NMAX;
    const int e_cnt = in_sizes[1] / 2;

    const int TPB = 256;
    const int nBlkN = (n + TPB - 1) / TPB;
    const int nThrE = e_cnt / EPT + 1;
    const int nBlkE = (nThrE + TPB - 1) / TPB;
    const int nWarps = (n + NPW - 1) / NPW;
    const int nBlkW = (nWarps * 32 + TPB - 1) / TPB;

    k_init<<<nBlkN, TPB>>>(edge, n);
    // fused: edge-count blocks first (start atomics early), proj blocks after
    k_deg_dot<<<nBlkE + nBlkW, TPB>>>(x, W, edge, e_cnt, n, nBlkE);
    k_pq<<<nBlkN, TPB>>>(n);
    k_hop1<<<nBlkE, TPB>>>(edge, e_cnt, n);
    k_mid<<<nBlkN, TPB>>>(n);
    k_hop2<<<nBlkE, TPB>>>(edge, e_cnt, n);
    k_final<<<nBlkN, TPB>>>(out, b, n);
}

// round 9
// speedup vs baseline: 1.0095x; 1.0095x over previous
#include <cuda_runtime.h>
#include <stdint.h>

#define NMAX 50000
#define DD 128
#define NPW 8   // nodes per warp in proj-dot

// Scratch (no device allocs allowed)
__device__ int   g_mode;        // 1 = indices are int64, 0 = int32
__device__ float g_deg[NMAX];
__device__ float g_y[NMAX];     // x . W
__device__ float g_p[NMAX];
__device__ float g_q[NMAX];     // p * y   (hop-1 message value)
__device__ float g_r[NMAX];     // p * t   (hop-2 message value)
__device__ float g_acc1[NMAX];  // sum of q[src] per dst
__device__ float g_acc2[NMAX];  // sum of r[src] per dst

// ---------------------------------------------------------------------------
// K1: detect dtype (warp 0 of block 0) + deg[i]=1 + zero accumulators
__global__ void k_init(const long long* __restrict__ edge, int n) {
    if (blockIdx.x == 0 && threadIdx.x < 32) {
        long long v = edge[threadIdx.x];
        unsigned ok = __ballot_sync(0xffffffffu, v >= 0 && v < (long long)n);
        if (threadIdx.x == 0) g_mode = (ok == 0xffffffffu) ? 1 : 0;
    }
    int i = blockIdx.x * blockDim.x + threadIdx.x;
    if (i < n) {
        g_deg[i]  = 1.0f;
        g_acc1[i] = 0.0f;
        g_acc2[i] = 0.0f;
    }
}

// ---------------------------------------------------------------------------
// K2 (fused, block-specialized):
//   blocks [0, edgeBlocks)   : deg[dst] += 1, one edge per thread
//   blocks [edgeBlocks, ...) : y[node] = x[node] . W   (warp handles NPW nodes)
__global__ void k_deg_dot(const float* __restrict__ x, const float* __restrict__ W,
                          const long long* __restrict__ edge,
                          int e_cnt, int n, int edgeBlocks) {
    if (blockIdx.x < edgeBlocks) {
        int e = blockIdx.x * blockDim.x + threadIdx.x;
        if (e < e_cnt) {
            int dst = g_mode ? (int)edge[e_cnt + e] : ((const int*)edge)[e_cnt + e];
            if ((unsigned)dst < (unsigned)n)
                atomicAdd(&g_deg[dst], 1.0f);
        }
    } else {
        int bid = blockIdx.x - edgeBlocks;
        int warp = (bid * blockDim.x + threadIdx.x) >> 5;
        int lane = threadIdx.x & 31;
        int base = warp * NPW;
        if (base >= n) return;

        float4 w = __ldg(&((const float4*)W)[lane]);

        float4 a[NPW];
        #pragma unroll
        for (int k = 0; k < NPW; k++) {
            int node = base + k;
            if (node < n)
                a[k] = ((const float4*)(x + (size_t)node * DD))[lane];
            else
                a[k] = make_float4(0.f, 0.f, 0.f, 0.f);
        }

        float s[NPW];
        #pragma unroll
        for (int k = 0; k < NPW; k++)
            s[k] = a[k].x * w.x + a[k].y * w.y + a[k].z * w.z + a[k].w * w.w;

        #pragma unroll
        for (int off = 16; off > 0; off >>= 1) {
            #pragma unroll
            for (int k = 0; k < NPW; k++)
                s[k] += __shfl_down_sync(0xffffffffu, s[k], off);
        }

        if (lane == 0) {
            #pragma unroll
            for (int k = 0; k < NPW; k++) {
                int node = base + k;
                if (node < n) g_y[node] = s[k];
            }
        }
    }
}

// ---------------------------------------------------------------------------
// K3: p = rsqrt(deg), q = p*y
__global__ void k_pq(int n) {
    int i = blockIdx.x * blockDim.x + threadIdx.x;
    if (i < n) {
        float p = rsqrtf(g_deg[i]);
        g_p[i] = p;
        g_q[i] = p * g_y[i];
    }
}

// ---------------------------------------------------------------------------
// Edge sweep: acc[dst] += val[src].  ONE edge per thread (max occupancy; the
// chip wants many warps with one outstanding gather each, not batched ILP).
__device__ __forceinline__ void edge_sweep(const long long* __restrict__ edge,
                                           int e_cnt, int n,
                                           const float* __restrict__ val,
                                           float* __restrict__ acc) {
    int e = blockIdx.x * blockDim.x + threadIdx.x;
    if (e < e_cnt) {
        int src, dst;
        if (g_mode) {
            src = (int)edge[e];
            dst = (int)edge[e_cnt + e];
        } else {
            const int* e32 = (const int*)edge;
            src = e32[e];
            dst = e32[e_cnt + e];
        }
        if ((unsigned)src < (unsigned)n && (unsigned)dst < (unsigned)n)
            atomicAdd(&acc[dst], val[src]);
    }
}

__global__ void k_hop1(const long long* __restrict__ edge, int e_cnt, int n) {
    edge_sweep(edge, e_cnt, n, g_q, g_acc1);
}

__global__ void k_hop2(const long long* __restrict__ edge, int e_cnt, int n) {
    edge_sweep(edge, e_cnt, n, g_r, g_acc2);
}

// ---------------------------------------------------------------------------
// K5: r = p*p*(q + acc1)
__global__ void k_mid(int n) {
    int i = blockIdx.x * blockDim.x + threadIdx.x;
    if (i < n) {
        float p = g_p[i];
        g_r[i] = p * p * (g_q[i] + g_acc1[i]);
    }
}

// K7: out[i] = p*(r + acc2) + b
__global__ void k_final(float* __restrict__ out, const float* __restrict__ b, int n) {
    int i = blockIdx.x * blockDim.x + threadIdx.x;
    if (i < n) {
        out[i] = g_p[i] * (g_r[i] + g_acc2[i]) + b[0];
    }
}

extern "C" void kernel_launch(void* const* d_in, const int* in_sizes, int n_in,
                              void* d_out, int out_size) {
    const float*     x    = (const float*)d_in[0];       // [N, 128]
    const long long* edge = (const long long*)d_in[1];   // [2, E] indices
    const float*     W    = (const float*)d_in[2];       // [1, 128]
    const float*     b    = (const float*)d_in[3];       // [1]
    float*           out  = (float*)d_out;               // [N]

    int n = in_sizes[0] / DD;
    if (n > NMAX) n = NMAX;
    const int e_cnt = in_sizes[1] / 2;

    const int TPB = 256;
    const int nBlkN = (n + TPB - 1) / TPB;
    const int nBlkE = (e_cnt + TPB - 1) / TPB;            // one edge / thread
    const int nWarps = (n + NPW - 1) / NPW;
    const int nBlkW = (nWarps * 32 + TPB - 1) / TPB;

    k_init<<<nBlkN, TPB>>>(edge, n);
    k_deg_dot<<<nBlkE + nBlkW, TPB>>>(x, W, edge, e_cnt, n, nBlkE);
    k_pq<<<nBlkN, TPB>>>(n);
    k_hop1<<<nBlkE, TPB>>>(edge, e_cnt, n);
    k_mid<<<nBlkN, TPB>>>(n);
    k_hop2<<<nBlkE, TPB>>>(edge, e_cnt, n);
    k_final<<<nBlkN, TPB>>>(out, b, n);
}